// round 1
// baseline (speedup 1.0000x reference)
#include <cuda_runtime.h>

#define SS    80
#define HID   512
#define NPIX  8192      // 8 images * 32*32
#define KCONV 720       // 80 * 9
#define CA_THRESH 0.01f

// Internal buffers (allocation-free: __device__ globals)
__device__ float g_state[SS * NPIX];
__device__ float g_tmp[SS * NPIX];
__device__ float g_perc[HID * NPIX];
__device__ float g_h[HID * NPIX];
__device__ unsigned char g_pre[NPIX];

// ---------------------------------------------------------------------------
// init
// ---------------------------------------------------------------------------
__global__ void k_zero_state() {
    int i = blockIdx.x * blockDim.x + threadIdx.x;
    if (i < SS * NPIX) g_state[i] = 0.f;
}

__global__ void k_init(const float* __restrict__ z) {
    // 8 * 80 threads: n = t / 80, c = t % 80; seed center pixel (16,16)
    int t = blockIdx.x * blockDim.x + threadIdx.x;
    if (t >= 8 * SS) return;
    int n = t / SS, c = t % SS;
    int p = n * 1024 + 16 * 32 + 16;
    float v = (c == 0) ? 1.0f : z[n * 100 + (c - 1)];
    g_state[c * NPIX + p] = v;
}

// ---------------------------------------------------------------------------
// 3x3 maxpool on a [NPIX] channel row (per-image, SAME padding w/ -inf)
// ---------------------------------------------------------------------------
__device__ __forceinline__ float maxpool3(const float* __restrict__ row, int p) {
    int x = p & 31, y = (p >> 5) & 31;
    float m = -1e30f;
    #pragma unroll
    for (int dy = -1; dy <= 1; dy++) {
        int yy = y + dy;
        if ((unsigned)yy >= 32u) continue;
        #pragma unroll
        for (int dx = -1; dx <= 1; dx++) {
            int xx = x + dx;
            if ((unsigned)xx >= 32u) continue;
            m = fmaxf(m, row[p + dy * 32 + dx]);
        }
    }
    return m;
}

__global__ void k_pre() {
    int p = blockIdx.x * blockDim.x + threadIdx.x;
    if (p >= NPIX) return;
    g_pre[p] = (maxpool3(g_state, p) > CA_THRESH) ? 1 : 0;
}

// ---------------------------------------------------------------------------
// GEMM1: perception[512][8192] = W1[512][720] (*) im2col(state) + b1
// 128x128x16 tile, 256 threads, 8x8 microtile. im2col gather fused in B load.
// ---------------------------------------------------------------------------
#define BM 128
#define BN 128
#define BK 16

__global__ __launch_bounds__(256) void k_gemm_conv(const float* __restrict__ W1,
                                                   const float* __restrict__ b1) {
    __shared__ float As[BK][BM];
    __shared__ float Bs[BK][BN];
    const int bm = blockIdx.y * BM;
    const int bn = blockIdx.x * BN;
    const int tid = threadIdx.x;
    const int tx = tid & 15, ty = tid >> 4;

    // fixed pixel for this thread's B-gather duties
    const int nb = tid & 127;
    const int p  = bn + nb;
    const int x  = p & 31, y = (p >> 5) & 31;
    const int kb = tid >> 7;   // 0 or 1

    float acc[8][8];
    #pragma unroll
    for (int i = 0; i < 8; i++)
        #pragma unroll
        for (int j = 0; j < 8; j++) acc[i][j] = 0.f;

    for (int k0 = 0; k0 < KCONV; k0 += BK) {
        // A tile: 2 float4 per thread, store transposed
        #pragma unroll
        for (int it = 0; it < 2; it++) {
            int f4 = tid + it * 256;          // 0..511
            int m  = f4 >> 2;                 // 0..127
            int kq = (f4 & 3) * 4;            // 0,4,8,12
            float4 a = *reinterpret_cast<const float4*>(&W1[(bm + m) * KCONV + k0 + kq]);
            As[kq + 0][m] = a.x; As[kq + 1][m] = a.y;
            As[kq + 2][m] = a.z; As[kq + 3][m] = a.w;
        }
        // B tile: fused im2col gather (8 scalar loads / thread)
        #pragma unroll
        for (int it = 0; it < 8; it++) {
            int k  = k0 + kb + it * 2;
            int ci = k / 9;
            int r  = k - ci * 9;              // ky*3 + kx
            int dy = r / 3 - 1;
            int dx = r - (dy + 1) * 3 - 1;
            int yy = y + dy, xx = x + dx;
            float v = 0.f;
            if ((unsigned)yy < 32u && (unsigned)xx < 32u)
                v = g_state[ci * NPIX + p + dy * 32 + dx];
            Bs[kb + it * 2][nb] = v;
        }
        __syncthreads();
        #pragma unroll
        for (int k = 0; k < BK; k++) {
            float a[8], b[8];
            #pragma unroll
            for (int i = 0; i < 8; i++) a[i] = As[k][ty + 16 * i];
            #pragma unroll
            for (int j = 0; j < 8; j++) b[j] = Bs[k][tx + 16 * j];
            #pragma unroll
            for (int i = 0; i < 8; i++)
                #pragma unroll
                for (int j = 0; j < 8; j++)
                    acc[i][j] = fmaf(a[i], b[j], acc[i][j]);
        }
        __syncthreads();
    }
    #pragma unroll
    for (int i = 0; i < 8; i++) {
        int m = bm + ty + 16 * i;
        float bias = b1[m];
        #pragma unroll
        for (int j = 0; j < 8; j++)
            g_perc[m * NPIX + bn + tx + 16 * j] = acc[i][j] + bias;
    }
}

// ---------------------------------------------------------------------------
// GEMM2: h[512][8192] = relu(W2[512][512] @ perception + b2)
// ---------------------------------------------------------------------------
__global__ __launch_bounds__(256) void k_gemm_h(const float* __restrict__ W2,
                                                const float* __restrict__ b2) {
    __shared__ float As[BK][BM];
    __shared__ float Bs[BK][BN];
    const int bm = blockIdx.y * BM;
    const int bn = blockIdx.x * BN;
    const int tid = threadIdx.x;
    const int tx = tid & 15, ty = tid >> 4;

    float acc[8][8];
    #pragma unroll
    for (int i = 0; i < 8; i++)
        #pragma unroll
        for (int j = 0; j < 8; j++) acc[i][j] = 0.f;

    for (int k0 = 0; k0 < HID; k0 += BK) {
        #pragma unroll
        for (int it = 0; it < 2; it++) {
            int f4 = tid + it * 256;
            int m  = f4 >> 2;
            int kq = (f4 & 3) * 4;
            float4 a = *reinterpret_cast<const float4*>(&W2[(bm + m) * HID + k0 + kq]);
            As[kq + 0][m] = a.x; As[kq + 1][m] = a.y;
            As[kq + 2][m] = a.z; As[kq + 3][m] = a.w;
        }
        #pragma unroll
        for (int it = 0; it < 2; it++) {
            int f4 = tid + it * 256;          // 0..511
            int k  = f4 >> 5;                 // 0..15
            int nq = (f4 & 31) * 4;           // 0..124
            float4 v = *reinterpret_cast<const float4*>(&g_perc[(k0 + k) * NPIX + bn + nq]);
            *reinterpret_cast<float4*>(&Bs[k][nq]) = v;
        }
        __syncthreads();
        #pragma unroll
        for (int k = 0; k < BK; k++) {
            float a[8], b[8];
            #pragma unroll
            for (int i = 0; i < 8; i++) a[i] = As[k][ty + 16 * i];
            #pragma unroll
            for (int j = 0; j < 8; j++) b[j] = Bs[k][tx + 16 * j];
            #pragma unroll
            for (int i = 0; i < 8; i++)
                #pragma unroll
                for (int j = 0; j < 8; j++)
                    acc[i][j] = fmaf(a[i], b[j], acc[i][j]);
        }
        __syncthreads();
    }
    #pragma unroll
    for (int i = 0; i < 8; i++) {
        int m = bm + ty + 16 * i;
        float bias = b2[m];
        #pragma unroll
        for (int j = 0; j < 8; j++)
            g_h[m * NPIX + bn + tx + 16 * j] = fmaxf(acc[i][j] + bias, 0.f);
    }
}

// ---------------------------------------------------------------------------
// GEMM3: tmp[80][8192] = W3[80][512] @ h + b3 + state   (state+updates)
// 80x64x16 tile, 256 threads, 5x4 microtile.
// ---------------------------------------------------------------------------
#define BM3 80
#define BN3 64

__global__ __launch_bounds__(256) void k_gemm_upd(const float* __restrict__ W3,
                                                  const float* __restrict__ b3) {
    __shared__ float As[BK][BM3];
    __shared__ float Bs[BK][BN3];
    const int bn = blockIdx.x * BN3;
    const int tid = threadIdx.x;
    const int tx = tid & 15, ty = tid >> 4;

    float acc[5][4];
    #pragma unroll
    for (int i = 0; i < 5; i++)
        #pragma unroll
        for (int j = 0; j < 4; j++) acc[i][j] = 0.f;

    for (int k0 = 0; k0 < HID; k0 += BK) {
        // A: 80*16 = 1280 scalar elems, 5/thread
        #pragma unroll
        for (int it = 0; it < 5; it++) {
            int f = tid + it * 256;           // 0..1279
            int m = f >> 4, k = f & 15;
            As[k][m] = W3[m * HID + k0 + k];
        }
        // B: 16*64 = 1024 elems = 256 float4, 1/thread
        {
            int k  = tid >> 4;                // 0..15
            int nq = (tid & 15) * 4;          // 0..60
            float4 v = *reinterpret_cast<const float4*>(&g_h[(k0 + k) * NPIX + bn + nq]);
            *reinterpret_cast<float4*>(&Bs[k][nq]) = v;
        }
        __syncthreads();
        #pragma unroll
        for (int k = 0; k < BK; k++) {
            float a[5], b[4];
            #pragma unroll
            for (int i = 0; i < 5; i++) a[i] = As[k][ty + 16 * i];
            #pragma unroll
            for (int j = 0; j < 4; j++) b[j] = Bs[k][tx + 16 * j];
            #pragma unroll
            for (int i = 0; i < 5; i++)
                #pragma unroll
                for (int j = 0; j < 4; j++)
                    acc[i][j] = fmaf(a[i], b[j], acc[i][j]);
        }
        __syncthreads();
    }
    #pragma unroll
    for (int i = 0; i < 5; i++) {
        int m = ty + 16 * i;                  // 0..79
        float bias = b3[m];
        #pragma unroll
        for (int j = 0; j < 4; j++) {
            int idx = m * NPIX + bn + tx + 16 * j;
            g_tmp[idx] = acc[i][j] + bias + g_state[idx];
        }
    }
}

// ---------------------------------------------------------------------------
// finalize: post-living, combine with pre, write masked state
// ---------------------------------------------------------------------------
__global__ void k_finalize() {
    int p = blockIdx.x * blockDim.x + threadIdx.x;
    if (p >= NPIX) return;
    float post = maxpool3(g_tmp, p);
    bool alive = (post > CA_THRESH) && g_pre[p];
    #pragma unroll 4
    for (int c = 0; c < SS; c++)
        g_state[c * NPIX + p] = alive ? g_tmp[c * NPIX + p] : 0.f;
}

__global__ void k_out(float* __restrict__ out) {
    int p = blockIdx.x * blockDim.x + threadIdx.x;
    if (p < NPIX) out[p] = g_state[p];
}

// ---------------------------------------------------------------------------
// launch
// ---------------------------------------------------------------------------
extern "C" void kernel_launch(void* const* d_in, const int* in_sizes, int n_in,
                              void* d_out, int out_size) {
    const float* z  = (const float*)d_in[0];
    const float* W1 = (const float*)d_in[1];
    const float* b1 = (const float*)d_in[2];
    const float* W2 = (const float*)d_in[3];
    const float* b2 = (const float*)d_in[4];
    const float* W3 = (const float*)d_in[5];
    const float* b3 = (const float*)d_in[6];

    k_zero_state<<<(SS * NPIX + 255) / 256, 256>>>();
    k_init<<<3, 256>>>(z);

    dim3 g12(NPIX / BN, HID / BM);   // (64, 4)
    for (int s = 0; s < 64; s++) {
        k_pre<<<NPIX / 256, 256>>>();
        k_gemm_conv<<<g12, 256>>>(W1, b1);
        k_gemm_h<<<g12, 256>>>(W2, b2);
        k_gemm_upd<<<NPIX / BN3, 256>>>(W3, b3);
        k_finalize<<<NPIX / 256, 256>>>();
    }
    k_out<<<NPIX / 256, 256>>>((float*)d_out);
}

// round 3
// speedup vs baseline: 1.1133x; 1.1133x over previous
#include <cuda_runtime.h>

#define SS    80
#define HID   512
#define NPIX  8192      // 8 images * 32*32
#define KCONV 720       // 80 * 9
#define CA_THRESH 0.01f

// Internal buffers (allocation-free: __device__ globals)
__device__ float g_state[SS * NPIX];
__device__ float g_tmp[SS * NPIX];
__device__ float g_perc[HID * NPIX];
__device__ float g_h[HID * NPIX];
__device__ unsigned char g_pre[NPIX];

// ---------------------------------------------------------------------------
// init
// ---------------------------------------------------------------------------
__global__ void k_zero_state() {
    int i = blockIdx.x * blockDim.x + threadIdx.x;
    if (i < SS * NPIX) g_state[i] = 0.f;
}

__global__ void k_init(const float* __restrict__ z) {
    int t = blockIdx.x * blockDim.x + threadIdx.x;
    if (t >= 8 * SS) return;
    int n = t / SS, c = t % SS;
    int p = n * 1024 + 16 * 32 + 16;
    float v = (c == 0) ? 1.0f : z[n * 100 + (c - 1)];
    g_state[c * NPIX + p] = v;
}

__device__ __forceinline__ float maxpool3(const float* __restrict__ row, int p) {
    int x = p & 31, y = (p >> 5) & 31;
    float m = -1e30f;
    #pragma unroll
    for (int dy = -1; dy <= 1; dy++) {
        int yy = y + dy;
        if ((unsigned)yy >= 32u) continue;
        #pragma unroll
        for (int dx = -1; dx <= 1; dx++) {
            int xx = x + dx;
            if ((unsigned)xx >= 32u) continue;
            m = fmaxf(m, row[p + dy * 32 + dx]);
        }
    }
    return m;
}

// initial pre-living (step 0 only; afterwards fused into finalize)
__global__ void k_pre() {
    int p = blockIdx.x * blockDim.x + threadIdx.x;
    if (p >= NPIX) return;
    g_pre[p] = (maxpool3(g_state, p) > CA_THRESH) ? 1 : 0;
}

// ---------------------------------------------------------------------------
// GEMM tile params: 128x128x16, 256 threads, 8x8 microtile (split 4+4),
// double-buffered smem, float4 LDS.
// ---------------------------------------------------------------------------
#define BM 128
#define BN 128
#define BK 16

#define MM_COMPUTE(CUR)                                                     \
    _Pragma("unroll")                                                       \
    for (int k = 0; k < BK; k++) {                                          \
        float4 a0 = *reinterpret_cast<const float4*>(&As[CUR][k][ty4]);     \
        float4 a1 = *reinterpret_cast<const float4*>(&As[CUR][k][ty4+64]);  \
        float4 b0 = *reinterpret_cast<const float4*>(&Bs[CUR][k][tx4]);     \
        float4 b1 = *reinterpret_cast<const float4*>(&Bs[CUR][k][tx4+64]);  \
        float a[8] = {a0.x,a0.y,a0.z,a0.w,a1.x,a1.y,a1.z,a1.w};             \
        float b[8] = {b0.x,b0.y,b0.z,b0.w,b1.x,b1.y,b1.z,b1.w};             \
        _Pragma("unroll")                                                   \
        for (int i = 0; i < 8; i++)                                         \
            _Pragma("unroll")                                               \
            for (int j = 0; j < 8; j++)                                     \
                acc[i][j] = fmaf(a[i], b[j], acc[i][j]);                    \
    }

// ---------------------------------------------------------------------------
// GEMM1: perception = W1 (*) im2col(state) + b1   (512 x 8192 x 720)
// ---------------------------------------------------------------------------
__global__ __launch_bounds__(256, 2) void k_gemm_conv(const float* __restrict__ W1,
                                                      const float* __restrict__ b1) {
    __shared__ float As[2][BK][BM];
    __shared__ float Bs[2][BK][BN];
    const int bm = blockIdx.y * BM;
    const int bn = blockIdx.x * BN;
    const int tid = threadIdx.x;
    const int tx4 = (tid & 15) * 4;
    const int ty4 = (tid >> 4) * 4;

    // B-gather identity for this thread
    const int nb = tid & 127;
    const int p  = bn + nb;
    const int x  = p & 31, y = (p >> 5) & 31;
    const int kb = tid >> 7;   // 0 or 1

    float acc[8][8];
    #pragma unroll
    for (int i = 0; i < 8; i++)
        #pragma unroll
        for (int j = 0; j < 8; j++) acc[i][j] = 0.f;

    // --- load first tile (k0 = 0) into buffer 0 ---
    #pragma unroll
    for (int it = 0; it < 2; it++) {
        int f4 = tid + it * 256;
        int m  = f4 >> 2;
        int kq = (f4 & 3) * 4;
        float4 a = *reinterpret_cast<const float4*>(&W1[(bm + m) * KCONV + kq]);
        As[0][kq + 0][m] = a.x; As[0][kq + 1][m] = a.y;
        As[0][kq + 2][m] = a.z; As[0][kq + 3][m] = a.w;
    }
    #pragma unroll
    for (int it = 0; it < 8; it++) {
        int k  = kb + it * 2;
        int ci = k / 9;
        int r  = k - ci * 9;
        int dy = r / 3 - 1;
        int dx = r - (dy + 1) * 3 - 1;
        int yy = y + dy, xx = x + dx;
        float v = 0.f;
        if ((unsigned)yy < 32u && (unsigned)xx < 32u)
            v = g_state[ci * NPIX + p + dy * 32 + dx];
        Bs[0][kb + it * 2][nb] = v;
    }
    __syncthreads();

    int cur = 0;
    for (int k0 = BK; k0 < KCONV; k0 += BK) {
        // prefetch next tile into registers
        float4 pa[2];
        #pragma unroll
        for (int it = 0; it < 2; it++) {
            int f4 = tid + it * 256;
            int m  = f4 >> 2;
            int kq = (f4 & 3) * 4;
            pa[it] = *reinterpret_cast<const float4*>(&W1[(bm + m) * KCONV + k0 + kq]);
        }
        float pb[8];
        #pragma unroll
        for (int it = 0; it < 8; it++) {
            int k  = k0 + kb + it * 2;
            int ci = k / 9;
            int r  = k - ci * 9;
            int dy = r / 3 - 1;
            int dx = r - (dy + 1) * 3 - 1;
            int yy = y + dy, xx = x + dx;
            float v = 0.f;
            if ((unsigned)yy < 32u && (unsigned)xx < 32u)
                v = g_state[ci * NPIX + p + dy * 32 + dx];
            pb[it] = v;
        }

        MM_COMPUTE(cur)

        int nxt = cur ^ 1;
        #pragma unroll
        for (int it = 0; it < 2; it++) {
            int f4 = tid + it * 256;
            int m  = f4 >> 2;
            int kq = (f4 & 3) * 4;
            As[nxt][kq + 0][m] = pa[it].x; As[nxt][kq + 1][m] = pa[it].y;
            As[nxt][kq + 2][m] = pa[it].z; As[nxt][kq + 3][m] = pa[it].w;
        }
        #pragma unroll
        for (int it = 0; it < 8; it++)
            Bs[nxt][kb + it * 2][nb] = pb[it];
        __syncthreads();
        cur = nxt;
    }
    MM_COMPUTE(cur)

    // epilogue: +bias, float4 stores
    #pragma unroll
    for (int i = 0; i < 8; i++) {
        int m = bm + ((i < 4) ? (ty4 + i) : (64 + ty4 + i - 4));
        float bias = b1[m];
        float4 v0 = make_float4(acc[i][0] + bias, acc[i][1] + bias,
                                acc[i][2] + bias, acc[i][3] + bias);
        float4 v1 = make_float4(acc[i][4] + bias, acc[i][5] + bias,
                                acc[i][6] + bias, acc[i][7] + bias);
        *reinterpret_cast<float4*>(&g_perc[m * NPIX + bn + tx4])      = v0;
        *reinterpret_cast<float4*>(&g_perc[m * NPIX + bn + tx4 + 64]) = v1;
    }
}

// ---------------------------------------------------------------------------
// GEMM2: h = relu(W2 @ perception + b2)   (512 x 8192 x 512)
// ---------------------------------------------------------------------------
__global__ __launch_bounds__(256, 2) void k_gemm_h(const float* __restrict__ W2,
                                                   const float* __restrict__ b2) {
    __shared__ float As[2][BK][BM];
    __shared__ float Bs[2][BK][BN];
    const int bm = blockIdx.y * BM;
    const int bn = blockIdx.x * BN;
    const int tid = threadIdx.x;
    const int tx4 = (tid & 15) * 4;
    const int ty4 = (tid >> 4) * 4;

    float acc[8][8];
    #pragma unroll
    for (int i = 0; i < 8; i++)
        #pragma unroll
        for (int j = 0; j < 8; j++) acc[i][j] = 0.f;

    // first tile
    #pragma unroll
    for (int it = 0; it < 2; it++) {
        int f4 = tid + it * 256;
        int m  = f4 >> 2;
        int kq = (f4 & 3) * 4;
        float4 a = *reinterpret_cast<const float4*>(&W2[(bm + m) * HID + kq]);
        As[0][kq + 0][m] = a.x; As[0][kq + 1][m] = a.y;
        As[0][kq + 2][m] = a.z; As[0][kq + 3][m] = a.w;
    }
    #pragma unroll
    for (int it = 0; it < 2; it++) {
        int f4 = tid + it * 256;
        int k  = f4 >> 5;
        int nq = (f4 & 31) * 4;
        float4 v = *reinterpret_cast<const float4*>(&g_perc[k * NPIX + bn + nq]);
        *reinterpret_cast<float4*>(&Bs[0][k][nq]) = v;
    }
    __syncthreads();

    int cur = 0;
    for (int k0 = BK; k0 < HID; k0 += BK) {
        float4 pa[2], pb[2];
        #pragma unroll
        for (int it = 0; it < 2; it++) {
            int f4 = tid + it * 256;
            int m  = f4 >> 2;
            int kq = (f4 & 3) * 4;
            pa[it] = *reinterpret_cast<const float4*>(&W2[(bm + m) * HID + k0 + kq]);
        }
        #pragma unroll
        for (int it = 0; it < 2; it++) {
            int f4 = tid + it * 256;
            int k  = f4 >> 5;
            int nq = (f4 & 31) * 4;
            pb[it] = *reinterpret_cast<const float4*>(&g_perc[(k0 + k) * NPIX + bn + nq]);
        }

        MM_COMPUTE(cur)

        int nxt = cur ^ 1;
        #pragma unroll
        for (int it = 0; it < 2; it++) {
            int f4 = tid + it * 256;
            int m  = f4 >> 2;
            int kq = (f4 & 3) * 4;
            As[nxt][kq + 0][m] = pa[it].x; As[nxt][kq + 1][m] = pa[it].y;
            As[nxt][kq + 2][m] = pa[it].z; As[nxt][kq + 3][m] = pa[it].w;
        }
        #pragma unroll
        for (int it = 0; it < 2; it++) {
            int f4 = tid + it * 256;
            int k  = f4 >> 5;
            int nq = (f4 & 31) * 4;
            *reinterpret_cast<float4*>(&Bs[nxt][k][nq]) = pb[it];
        }
        __syncthreads();
        cur = nxt;
    }
    MM_COMPUTE(cur)

    #pragma unroll
    for (int i = 0; i < 8; i++) {
        int m = bm + ((i < 4) ? (ty4 + i) : (64 + ty4 + i - 4));
        float bias = b2[m];
        float4 v0 = make_float4(fmaxf(acc[i][0] + bias, 0.f), fmaxf(acc[i][1] + bias, 0.f),
                                fmaxf(acc[i][2] + bias, 0.f), fmaxf(acc[i][3] + bias, 0.f));
        float4 v1 = make_float4(fmaxf(acc[i][4] + bias, 0.f), fmaxf(acc[i][5] + bias, 0.f),
                                fmaxf(acc[i][6] + bias, 0.f), fmaxf(acc[i][7] + bias, 0.f));
        *reinterpret_cast<float4*>(&g_h[m * NPIX + bn + tx4])      = v0;
        *reinterpret_cast<float4*>(&g_h[m * NPIX + bn + tx4 + 64]) = v1;
    }
}

// ---------------------------------------------------------------------------
// GEMM3: tmp = W3 @ h + b3 + state   (80 x 8192 x 512)
// ---------------------------------------------------------------------------
#define BM3 80
#define BN3 64

__global__ __launch_bounds__(256) void k_gemm_upd(const float* __restrict__ W3,
                                                  const float* __restrict__ b3) {
    __shared__ float As[BK][BM3];
    __shared__ float Bs[BK][BN3];
    const int bn = blockIdx.x * BN3;
    const int tid = threadIdx.x;
    const int tx = tid & 15, ty = tid >> 4;

    float acc[5][4];
    #pragma unroll
    for (int i = 0; i < 5; i++)
        #pragma unroll
        for (int j = 0; j < 4; j++) acc[i][j] = 0.f;

    for (int k0 = 0; k0 < HID; k0 += BK) {
        #pragma unroll
        for (int it = 0; it < 5; it++) {
            int f = tid + it * 256;
            int m = f >> 4, k = f & 15;
            As[k][m] = W3[m * HID + k0 + k];
        }
        {
            int k  = tid >> 4;
            int nq = (tid & 15) * 4;
            float4 v = *reinterpret_cast<const float4*>(&g_h[(k0 + k) * NPIX + bn + nq]);
            *reinterpret_cast<float4*>(&Bs[k][nq]) = v;
        }
        __syncthreads();
        #pragma unroll
        for (int k = 0; k < BK; k++) {
            float a[5], b[4];
            #pragma unroll
            for (int i = 0; i < 5; i++) a[i] = As[k][ty + 16 * i];
            #pragma unroll
            for (int j = 0; j < 4; j++) b[j] = Bs[k][tx + 16 * j];
            #pragma unroll
            for (int i = 0; i < 5; i++)
                #pragma unroll
                for (int j = 0; j < 4; j++)
                    acc[i][j] = fmaf(a[i], b[j], acc[i][j]);
        }
        __syncthreads();
    }
    #pragma unroll
    for (int i = 0; i < 5; i++) {
        int m = ty + 16 * i;
        float bias = b3[m];
        #pragma unroll
        for (int j = 0; j < 4; j++) {
            int idx = m * NPIX + bn + tx + 16 * j;
            g_tmp[idx] = acc[i][j] + bias + g_state[idx];
        }
    }
}

// ---------------------------------------------------------------------------
// finalize (fused): post-living of tmp, combine with pre, write masked state,
// AND compute pre-living for the NEXT step from the new state.
// One block per image (1024 pixels, 256 threads x 4 pixels).
// ---------------------------------------------------------------------------
__device__ __forceinline__ float maxpool_s(const float* s0, int pp) {
    int x = pp & 31, y = pp >> 5;
    float m = -1e30f;
    #pragma unroll
    for (int dy = -1; dy <= 1; dy++) {
        int yy = y + dy;
        if ((unsigned)yy >= 32u) continue;
        #pragma unroll
        for (int dx = -1; dx <= 1; dx++) {
            int xx = x + dx;
            if ((unsigned)xx >= 32u) continue;
            m = fmaxf(m, s0[pp + dy * 32 + dx]);
        }
    }
    return m;
}

__global__ __launch_bounds__(256) void k_finalize() {
    __shared__ float s0[1024];
    __shared__ unsigned char alv[1024];
    const int base = blockIdx.x * 1024;
    const int t = threadIdx.x;

    #pragma unroll
    for (int r = 0; r < 4; r++) {
        int pp = t + r * 256;
        s0[pp] = g_tmp[base + pp];
    }
    __syncthreads();

    #pragma unroll
    for (int r = 0; r < 4; r++) {
        int pp = t + r * 256;
        float post = maxpool_s(s0, pp);
        alv[pp] = (post > CA_THRESH) && g_pre[base + pp];
    }
    __syncthreads();

    // write masked state; rewrite s0 with the new channel-0 values
    #pragma unroll
    for (int r = 0; r < 4; r++) {
        int pp = t + r * 256;
        bool a = alv[pp];
        #pragma unroll 4
        for (int c = 0; c < SS; c++) {
            int idx = c * NPIX + base + pp;
            g_state[idx] = a ? g_tmp[idx] : 0.f;
        }
        s0[pp] = a ? s0[pp] : 0.f;
    }
    __syncthreads();

    // pre-living for next step from new state channel 0
    #pragma unroll
    for (int r = 0; r < 4; r++) {
        int pp = t + r * 256;
        g_pre[base + pp] = (maxpool_s(s0, pp) > CA_THRESH) ? 1 : 0;
    }
}

__global__ void k_out(float* __restrict__ out) {
    int p = blockIdx.x * blockDim.x + threadIdx.x;
    if (p < NPIX) out[p] = g_state[p];
}

// ---------------------------------------------------------------------------
// launch
// ---------------------------------------------------------------------------
extern "C" void kernel_launch(void* const* d_in, const int* in_sizes, int n_in,
                              void* d_out, int out_size) {
    const float* z  = (const float*)d_in[0];
    const float* W1 = (const float*)d_in[1];
    const float* b1 = (const float*)d_in[2];
    const float* W2 = (const float*)d_in[3];
    const float* b2 = (const float*)d_in[4];
    const float* W3 = (const float*)d_in[5];
    const float* b3 = (const float*)d_in[6];

    k_zero_state<<<(SS * NPIX + 255) / 256, 256>>>();
    k_init<<<3, 256>>>(z);
    k_pre<<<NPIX / 256, 256>>>();   // pre-living for step 0

    dim3 g12(NPIX / BN, HID / BM);   // (64, 4)
    for (int s = 0; s < 64; s++) {
        k_gemm_conv<<<g12, 256>>>(W1, b1);
        k_gemm_h<<<g12, 256>>>(W2, b2);
        k_gemm_upd<<<NPIX / BN3, 256>>>(W3, b3);
        k_finalize<<<8, 256>>>();
    }
    k_out<<<NPIX / 256, 256>>>((float*)d_out);
}

// round 9
// speedup vs baseline: 1.1500x; 1.0329x over previous
#include <cuda_runtime.h>
#include <cstdint>

#define SS    80
#define HID   512
#define NPIX  8192      // 8 images * 32*32
#define KCONV 720       // 80 * 9
#define CA_THRESH 0.01f

// Internal buffers (allocation-free: __device__ globals)
__device__ float g_state[SS * NPIX];
__device__ float g_tmp[SS * NPIX];
__device__ float g_perc[HID * NPIX];
__device__ float g_h[HID * NPIX];
__device__ unsigned char g_pre[NPIX];

// ---------------------------------------------------------------------------
// packed fp32x2 helpers (sm_103a FFMA2 path, per B300 SASS quickref)
// ---------------------------------------------------------------------------
__device__ __forceinline__ uint64_t pack2(float x, float y) {
    uint64_t r; asm("mov.b64 %0, {%1, %2};" : "=l"(r) : "f"(x), "f"(y));
    return r;
}
__device__ __forceinline__ void unpack2(uint64_t v, float& x, float& y) {
    asm("mov.b64 {%0, %1}, %2;" : "=f"(x), "=f"(y) : "l"(v));
}
__device__ __forceinline__ void fma2(uint64_t& d, uint64_t a, uint64_t b) {
    asm("fma.rn.f32x2 %0, %1, %2, %0;" : "+l"(d) : "l"(a), "l"(b));
}

// ---------------------------------------------------------------------------
// init
// ---------------------------------------------------------------------------
__global__ void k_zero_state() {
    int i = blockIdx.x * blockDim.x + threadIdx.x;
    if (i < SS * NPIX) g_state[i] = 0.f;
}

__global__ void k_init(const float* __restrict__ z) {
    int t = blockIdx.x * blockDim.x + threadIdx.x;
    if (t >= 8 * SS) return;
    int n = t / SS, c = t % SS;
    int p = n * 1024 + 16 * 32 + 16;
    float v = (c == 0) ? 1.0f : z[n * 100 + (c - 1)];
    g_state[c * NPIX + p] = v;
}

__device__ __forceinline__ float maxpool3(const float* __restrict__ row, int p) {
    int x = p & 31, y = (p >> 5) & 31;
    float m = -1e30f;
    #pragma unroll
    for (int dy = -1; dy <= 1; dy++) {
        int yy = y + dy;
        if ((unsigned)yy >= 32u) continue;
        #pragma unroll
        for (int dx = -1; dx <= 1; dx++) {
            int xx = x + dx;
            if ((unsigned)xx >= 32u) continue;
            m = fmaxf(m, row[p + dy * 32 + dx]);
        }
    }
    return m;
}

// initial pre-living (step 0 only; afterwards fused into finalize)
__global__ void k_pre() {
    int p = blockIdx.x * blockDim.x + threadIdx.x;
    if (p >= NPIX) return;
    g_pre[p] = (maxpool3(g_state, p) > CA_THRESH) ? 1 : 0;
}

// ---------------------------------------------------------------------------
// GEMM tile params: 128x128x16, 256 threads, 8x8 microtile (split 4+4),
// double-buffered smem. Inner loop uses packed fma.rn.f32x2:
//  acc2[i][q] holds column pair; b-pairs are aligned LDS.64 of adjacent floats.
// ---------------------------------------------------------------------------
#define BM 128
#define BN 128
#define BK 16

#define MM_COMPUTE2(CUR)                                                      \
    _Pragma("unroll")                                                         \
    for (int k = 0; k < BK; k++) {                                            \
        float4 a0 = *reinterpret_cast<const float4*>(&As[CUR][k][ty4]);       \
        float4 a1 = *reinterpret_cast<const float4*>(&As[CUR][k][ty4+64]);    \
        uint64_t ap[8];                                                       \
        ap[0] = pack2(a0.x, a0.x); ap[1] = pack2(a0.y, a0.y);                 \
        ap[2] = pack2(a0.z, a0.z); ap[3] = pack2(a0.w, a0.w);                 \
        ap[4] = pack2(a1.x, a1.x); ap[5] = pack2(a1.y, a1.y);                 \
        ap[6] = pack2(a1.z, a1.z); ap[7] = pack2(a1.w, a1.w);                 \
        uint64_t b0 = *reinterpret_cast<const uint64_t*>(&Bs[CUR][k][tx4]);   \
        uint64_t b1 = *reinterpret_cast<const uint64_t*>(&Bs[CUR][k][tx4+2]); \
        uint64_t b2 = *reinterpret_cast<const uint64_t*>(&Bs[CUR][k][tx4+64]);\
        uint64_t b3 = *reinterpret_cast<const uint64_t*>(&Bs[CUR][k][tx4+66]);\
        _Pragma("unroll")                                                     \
        for (int i = 0; i < 8; i++) {                                         \
            fma2(acc2[i][0], ap[i], b0);                                      \
            fma2(acc2[i][1], ap[i], b1);                                      \
            fma2(acc2[i][2], ap[i], b2);                                      \
            fma2(acc2[i][3], ap[i], b3);                                      \
        }                                                                     \
    }

// ---------------------------------------------------------------------------
// GEMM1: perception = W1 (*) im2col(state) + b1   (512 x 8192 x 720)
// ---------------------------------------------------------------------------
__global__ __launch_bounds__(256, 2) void k_gemm_conv(const float* __restrict__ W1,
                                                      const float* __restrict__ b1) {
    __shared__ float As[2][BK][BM];
    __shared__ float Bs[2][BK][BN];
    const int bm = blockIdx.y * BM;
    const int bn = blockIdx.x * BN;
    const int tid = threadIdx.x;
    const int tx4 = (tid & 15) * 4;
    const int ty4 = (tid >> 4) * 4;

    // B-gather identity for this thread
    const int nb = tid & 127;
    const int p  = bn + nb;
    const int x  = p & 31, y = (p >> 5) & 31;
    const int kb = tid >> 7;   // 0 or 1

    uint64_t acc2[8][4];
    #pragma unroll
    for (int i = 0; i < 8; i++)
        #pragma unroll
        for (int q = 0; q < 4; q++) acc2[i][q] = 0ull;

    // --- load first tile (k0 = 0) into buffer 0 ---
    #pragma unroll
    for (int it = 0; it < 2; it++) {
        int f4 = tid + it * 256;
        int m  = f4 >> 2;
        int kq = (f4 & 3) * 4;
        float4 a = *reinterpret_cast<const float4*>(&W1[(bm + m) * KCONV + kq]);
        As[0][kq + 0][m] = a.x; As[0][kq + 1][m] = a.y;
        As[0][kq + 2][m] = a.z; As[0][kq + 3][m] = a.w;
    }
    #pragma unroll
    for (int it = 0; it < 8; it++) {
        int k  = kb + it * 2;
        int ci = k / 9;
        int r  = k - ci * 9;
        int dy = r / 3 - 1;
        int dx = r - (dy + 1) * 3 - 1;
        int yy = y + dy, xx = x + dx;
        float v = 0.f;
        if ((unsigned)yy < 32u && (unsigned)xx < 32u)
            v = g_state[ci * NPIX + p + dy * 32 + dx];
        Bs[0][kb + it * 2][nb] = v;
    }
    __syncthreads();

    int cur = 0;
    for (int k0 = BK; k0 < KCONV; k0 += BK) {
        // prefetch next tile into registers
        float4 pa[2];
        #pragma unroll
        for (int it = 0; it < 2; it++) {
            int f4 = tid + it * 256;
            int m  = f4 >> 2;
            int kq = (f4 & 3) * 4;
            pa[it] = *reinterpret_cast<const float4*>(&W1[(bm + m) * KCONV + k0 + kq]);
        }
        float pb[8];
        #pragma unroll
        for (int it = 0; it < 8; it++) {
            int k  = k0 + kb + it * 2;
            int ci = k / 9;
            int r  = k - ci * 9;
            int dy = r / 3 - 1;
            int dx = r - (dy + 1) * 3 - 1;
            int yy = y + dy, xx = x + dx;
            float v = 0.f;
            if ((unsigned)yy < 32u && (unsigned)xx < 32u)
                v = g_state[ci * NPIX + p + dy * 32 + dx];
            pb[it] = v;
        }

        MM_COMPUTE2(cur)

        int nxt = cur ^ 1;
        #pragma unroll
        for (int it = 0; it < 2; it++) {
            int f4 = tid + it * 256;
            int m  = f4 >> 2;
            int kq = (f4 & 3) * 4;
            As[nxt][kq + 0][m] = pa[it].x; As[nxt][kq + 1][m] = pa[it].y;
            As[nxt][kq + 2][m] = pa[it].z; As[nxt][kq + 3][m] = pa[it].w;
        }
        #pragma unroll
        for (int it = 0; it < 8; it++)
            Bs[nxt][kb + it * 2][nb] = pb[it];
        __syncthreads();
        cur = nxt;
    }
    MM_COMPUTE2(cur)

    // epilogue: +bias, float4 stores
    #pragma unroll
    for (int i = 0; i < 8; i++) {
        int m = bm + ((i < 4) ? (ty4 + i) : (64 + ty4 + i - 4));
        float bias = b1[m];
        float c0, c1, c2, c3, c4, c5, c6, c7;
        unpack2(acc2[i][0], c0, c1); unpack2(acc2[i][1], c2, c3);
        unpack2(acc2[i][2], c4, c5); unpack2(acc2[i][3], c6, c7);
        float4 v0 = make_float4(c0 + bias, c1 + bias, c2 + bias, c3 + bias);
        float4 v1 = make_float4(c4 + bias, c5 + bias, c6 + bias, c7 + bias);
        *reinterpret_cast<float4*>(&g_perc[m * NPIX + bn + tx4])      = v0;
        *reinterpret_cast<float4*>(&g_perc[m * NPIX + bn + tx4 + 64]) = v1;
    }
}

// ---------------------------------------------------------------------------
// GEMM2: h = relu(W2 @ perception + b2)   (512 x 8192 x 512)
// ---------------------------------------------------------------------------
__global__ __launch_bounds__(256, 2) void k_gemm_h(const float* __restrict__ W2,
                                                   const float* __restrict__ b2) {
    __shared__ float As[2][BK][BM];
    __shared__ float Bs[2][BK][BN];
    const int bm = blockIdx.y * BM;
    const int bn = blockIdx.x * BN;
    const int tid = threadIdx.x;
    const int tx4 = (tid & 15) * 4;
    const int ty4 = (tid >> 4) * 4;

    uint64_t acc2[8][4];
    #pragma unroll
    for (int i = 0; i < 8; i++)
        #pragma unroll
        for (int q = 0; q < 4; q++) acc2[i][q] = 0ull;

    // first tile
    #pragma unroll
    for (int it = 0; it < 2; it++) {
        int f4 = tid + it * 256;
        int m  = f4 >> 2;
        int kq = (f4 & 3) * 4;
        float4 a = *reinterpret_cast<const float4*>(&W2[(bm + m) * HID + kq]);
        As[0][kq + 0][m] = a.x; As[0][kq + 1][m] = a.y;
        As[0][kq + 2][m] = a.z; As[0][kq + 3][m] = a.w;
    }
    #pragma unroll
    for (int it = 0; it < 2; it++) {
        int f4 = tid + it * 256;
        int k  = f4 >> 5;
        int nq = (f4 & 31) * 4;
        float4 v = *reinterpret_cast<const float4*>(&g_perc[k * NPIX + bn + nq]);
        *reinterpret_cast<float4*>(&Bs[0][k][nq]) = v;
    }
    __syncthreads();

    int cur = 0;
    for (int k0 = BK; k0 < HID; k0 += BK) {
        float4 pa[2], pb[2];
        #pragma unroll
        for (int it = 0; it < 2; it++) {
            int f4 = tid + it * 256;
            int m  = f4 >> 2;
            int kq = (f4 & 3) * 4;
            pa[it] = *reinterpret_cast<const float4*>(&W2[(bm + m) * HID + k0 + kq]);
        }
        #pragma unroll
        for (int it = 0; it < 2; it++) {
            int f4 = tid + it * 256;
            int k  = f4 >> 5;
            int nq = (f4 & 31) * 4;
            pb[it] = *reinterpret_cast<const float4*>(&g_perc[(k0 + k) * NPIX + bn + nq]);
        }

        MM_COMPUTE2(cur)

        int nxt = cur ^ 1;
        #pragma unroll
        for (int it = 0; it < 2; it++) {
            int f4 = tid + it * 256;
            int m  = f4 >> 2;
            int kq = (f4 & 3) * 4;
            As[nxt][kq + 0][m] = pa[it].x; As[nxt][kq + 1][m] = pa[it].y;
            As[nxt][kq + 2][m] = pa[it].z; As[nxt][kq + 3][m] = pa[it].w;
        }
        #pragma unroll
        for (int it = 0; it < 2; it++) {
            int f4 = tid + it * 256;
            int k  = f4 >> 5;
            int nq = (f4 & 31) * 4;
            *reinterpret_cast<float4*>(&Bs[nxt][k][nq]) = pb[it];
        }
        __syncthreads();
        cur = nxt;
    }
    MM_COMPUTE2(cur)

    #pragma unroll
    for (int i = 0; i < 8; i++) {
        int m = bm + ((i < 4) ? (ty4 + i) : (64 + ty4 + i - 4));
        float bias = b2[m];
        float c0, c1, c2, c3, c4, c5, c6, c7;
        unpack2(acc2[i][0], c0, c1); unpack2(acc2[i][1], c2, c3);
        unpack2(acc2[i][2], c4, c5); unpack2(acc2[i][3], c6, c7);
        float4 v0 = make_float4(fmaxf(c0 + bias, 0.f), fmaxf(c1 + bias, 0.f),
                                fmaxf(c2 + bias, 0.f), fmaxf(c3 + bias, 0.f));
        float4 v1 = make_float4(fmaxf(c4 + bias, 0.f), fmaxf(c5 + bias, 0.f),
                                fmaxf(c6 + bias, 0.f), fmaxf(c7 + bias, 0.f));
        *reinterpret_cast<float4*>(&g_h[m * NPIX + bn + tx4])      = v0;
        *reinterpret_cast<float4*>(&g_h[m * NPIX + bn + tx4 + 64]) = v1;
    }
}

// ---------------------------------------------------------------------------
// GEMM3: tmp = W3 @ h + b3 + state   (80 x 8192 x 512) — unchanged from R3
// ---------------------------------------------------------------------------
#define BM3 80
#define BN3 64

__global__ __launch_bounds__(256) void k_gemm_upd(const float* __restrict__ W3,
                                                  const float* __restrict__ b3) {
    __shared__ float As[BK][BM3];
    __shared__ float Bs[BK][BN3];
    const int bn = blockIdx.x * BN3;
    const int tid = threadIdx.x;
    const int tx = tid & 15, ty = tid >> 4;

    float acc[5][4];
    #pragma unroll
    for (int i = 0; i < 5; i++)
        #pragma unroll
        for (int j = 0; j < 4; j++) acc[i][j] = 0.f;

    for (int k0 = 0; k0 < HID; k0 += BK) {
        #pragma unroll
        for (int it = 0; it < 5; it++) {
            int f = tid + it * 256;
            int m = f >> 4, k = f & 15;
            As[k][m] = W3[m * HID + k0 + k];
        }
        {
            int k  = tid >> 4;
            int nq = (tid & 15) * 4;
            float4 v = *reinterpret_cast<const float4*>(&g_h[(k0 + k) * NPIX + bn + nq]);
            *reinterpret_cast<float4*>(&Bs[k][nq]) = v;
        }
        __syncthreads();
        #pragma unroll
        for (int k = 0; k < BK; k++) {
            float a[5], b[4];
            #pragma unroll
            for (int i = 0; i < 5; i++) a[i] = As[k][ty + 16 * i];
            #pragma unroll
            for (int j = 0; j < 4; j++) b[j] = Bs[k][tx + 16 * j];
            #pragma unroll
            for (int i = 0; i < 5; i++)
                #pragma unroll
                for (int j = 0; j < 4; j++)
                    acc[i][j] = fmaf(a[i], b[j], acc[i][j]);
        }
        __syncthreads();
    }
    #pragma unroll
    for (int i = 0; i < 5; i++) {
        int m = ty + 16 * i;
        float bias = b3[m];
        #pragma unroll
        for (int j = 0; j < 4; j++) {
            int idx = m * NPIX + bn + tx + 16 * j;
            g_tmp[idx] = acc[i][j] + bias + g_state[idx];
        }
    }
}

// ---------------------------------------------------------------------------
// finalize (fused): post-living, combine with pre, write masked state,
// and compute pre-living for the NEXT step. One block per image.
// ---------------------------------------------------------------------------
__device__ __forceinline__ float maxpool_s(const float* s0, int pp) {
    int x = pp & 31, y = pp >> 5;
    float m = -1e30f;
    #pragma unroll
    for (int dy = -1; dy <= 1; dy++) {
        int yy = y + dy;
        if ((unsigned)yy >= 32u) continue;
        #pragma unroll
        for (int dx = -1; dx <= 1; dx++) {
            int xx = x + dx;
            if ((unsigned)xx >= 32u) continue;
            m = fmaxf(m, s0[pp + dy * 32 + dx]);
        }
    }
    return m;
}

__global__ __launch_bounds__(256) void k_finalize() {
    __shared__ float s0[1024];
    __shared__ unsigned char alv[1024];
    const int base = blockIdx.x * 1024;
    const int t = threadIdx.x;

    #pragma unroll
    for (int r = 0; r < 4; r++) {
        int pp = t + r * 256;
        s0[pp] = g_tmp[base + pp];
    }
    __syncthreads();

    #pragma unroll
    for (int r = 0; r < 4; r++) {
        int pp = t + r * 256;
        float post = maxpool_s(s0, pp);
        alv[pp] = (post > CA_THRESH) && g_pre[base + pp];
    }
    __syncthreads();

    #pragma unroll
    for (int r = 0; r < 4; r++) {
        int pp = t + r * 256;
        bool a = alv[pp];
        #pragma unroll 4
        for (int c = 0; c < SS; c++) {
            int idx = c * NPIX + base + pp;
            g_state[idx] = a ? g_tmp[idx] : 0.f;
        }
        s0[pp] = a ? s0[pp] : 0.f;
    }
    __syncthreads();

    #pragma unroll
    for (int r = 0; r < 4; r++) {
        int pp = t + r * 256;
        g_pre[base + pp] = (maxpool_s(s0, pp) > CA_THRESH) ? 1 : 0;
    }
}

__global__ void k_out(float* __restrict__ out) {
    int p = blockIdx.x * blockDim.x + threadIdx.x;
    if (p < NPIX) out[p] = g_state[p];
}

// ---------------------------------------------------------------------------
// launch
// ---------------------------------------------------------------------------
extern "C" void kernel_launch(void* const* d_in, const int* in_sizes, int n_in,
                              void* d_out, int out_size) {
    const float* z  = (const float*)d_in[0];
    const float* W1 = (const float*)d_in[1];
    const float* b1 = (const float*)d_in[2];
    const float* W2 = (const float*)d_in[3];
    const float* b2 = (const float*)d_in[4];
    const float* W3 = (const float*)d_in[5];
    const float* b3 = (const float*)d_in[6];

    k_zero_state<<<(SS * NPIX + 255) / 256, 256>>>();
    k_init<<<3, 256>>>(z);
    k_pre<<<NPIX / 256, 256>>>();   // pre-living for step 0

    dim3 g12(NPIX / BN, HID / BM);   // (64, 4)
    for (int s = 0; s < 64; s++) {
        k_gemm_conv<<<g12, 256>>>(W1, b1);
        k_gemm_h<<<g12, 256>>>(W2, b2);
        k_gemm_upd<<<NPIX / BN3, 256>>>(W3, b3);
        k_finalize<<<8, 256>>>();
    }
    k_out<<<NPIX / 256, 256>>>((float*)d_out);
}